// round 1
// baseline (speedup 1.0000x reference)
#include <cuda_runtime.h>
#include <math.h>

// Problem constants
#define IMG_H 256
#define IMG_W 256
#define BATCH 4
#define CHANS 5
#define TILE  32
#define HALO  3                     // dil needs +-2, conv of dil needs +-1 => 3
#define SIGDIM (TILE + 2*HALO)      // 38
#define DILDIM (TILE + 2)           // 34 (tile +-1)
#define N_ELEMS (BATCH * IMG_H * IMG_W)   // 262144

__global__ __launch_bounds__(1024)
void containment_loss_kernel(const float* __restrict__ pred,
                             const float* __restrict__ target,
                             float* __restrict__ out)
{
    __shared__ float s_sig[SIGDIM][SIGDIM + 2];   // sigmoid(10*(t-0.5)), -inf OOB
    __shared__ float s_dil[DILDIM][DILDIM + 2];   // 5x5 max dilation, rel coord [-1,32]
    __shared__ float s_red[32];

    const int b   = blockIdx.z;
    const int ty0 = blockIdx.y * TILE;
    const int tx0 = blockIdx.x * TILE;
    const int tid = threadIdx.y * TILE + threadIdx.x;

    const float* t0 = target + (size_t)b * CHANS * IMG_H * IMG_W;                   // channel 0
    const float* p1 = pred   + (size_t)b * CHANS * IMG_H * IMG_W + IMG_H * IMG_W;   // channel 1

    // ---- Stage 1: sigmoid tile with halo-3; out-of-image = -inf (dilation pad) ----
    for (int i = tid; i < SIGDIM * SIGDIM; i += TILE * TILE) {
        int iy = i / SIGDIM, ix = i % SIGDIM;
        int gy = ty0 + iy - HALO;
        int gx = tx0 + ix - HALO;
        float v = -INFINITY;
        if (gy >= 0 && gy < IMG_H && gx >= 0 && gx < IMG_W) {
            float t = t0[gy * IMG_W + gx];
            v = 1.0f / (1.0f + expf(-10.0f * (t - 0.5f)));
        }
        s_sig[iy][ix] = v;
    }
    __syncthreads();

    // ---- Stage 2: 5x5 max dilation on rel coords [-1, 32] (index shift +1) ----
    // s_dil[iy][ix] corresponds to rel coord (iy-1, ix-1); its s_sig center is (iy+2, ix+2).
    for (int i = tid; i < DILDIM * DILDIM; i += TILE * TILE) {
        int iy = i / DILDIM, ix = i % DILDIM;
        float m = -INFINITY;
        #pragma unroll
        for (int dy = 0; dy < 5; dy++)
            #pragma unroll
            for (int dx = 0; dx < 5; dx++)
                m = fmaxf(m, s_sig[iy + dy][ix + dx]);
        s_dil[iy][ix] = m;
    }
    __syncthreads();

    // ---- Stage 3: 3x3 weighted sum of (1 - dil) with replicate clamping ----
    const float w_e = expf(-1.0f / 0.35f);            // edge weight
    const float w_d = expf(-sqrtf(2.0f) / 0.35f);     // diagonal weight

    const int py = threadIdx.y, px = threadIdx.x;
    const int gy = ty0 + py,    gx = tx0 + px;

    float conv = 0.0f;
    #pragma unroll
    for (int dy = -1; dy <= 1; dy++) {
        #pragma unroll
        for (int dx = -1; dx <= 1; dx++) {
            int cy = min(max(gy + dy, 0), IMG_H - 1) - ty0 + 1;   // s_dil index
            int cx = min(max(gx + dx, 0), IMG_W - 1) - tx0 + 1;
            float w = (dy == 0 && dx == 0) ? 1.0f
                    : ((dy == 0 || dx == 0) ? w_e : w_d);
            conv += w * (1.0f - s_dil[cy][cx]);
        }
    }

    // cdt = -0.35*log(conv); fires only at scan iter 0 (boundary monotone, conv>0);
    // dist = cdt if cdt > 0 else 0; penalty = clip(dist/10, 0, 1)
    float cdt = -0.35f * logf(conv);
    float pen = 0.0f;
    if (cdt > 0.0f) {
        pen = cdt / 10.0f;
        pen = fminf(fmaxf(pen, 0.0f), 1.0f);
    }
    float dil_c = s_dil[py + 1][px + 1];
    float viol  = p1[gy * IMG_W + gx] * (1.0f - dil_c) * pen;

    // ---- Block reduction -> atomic add of partial mean ----
    #pragma unroll
    for (int off = 16; off > 0; off >>= 1)
        viol += __shfl_down_sync(0xFFFFFFFFu, viol, off);
    if ((tid & 31) == 0) s_red[tid >> 5] = viol;
    __syncthreads();
    if (tid < 32) {
        float v = s_red[tid];
        #pragma unroll
        for (int off = 16; off > 0; off >>= 1)
            v += __shfl_down_sync(0xFFFFFFFFu, v, off);
        if (tid == 0)
            atomicAdd(out, v * (1.0f / (float)N_ELEMS));
    }
}

extern "C" void kernel_launch(void* const* d_in, const int* in_sizes, int n_in,
                              void* d_out, int out_size)
{
    const float* pred   = (const float*)d_in[0];
    const float* target = (const float*)d_in[1];
    float* out = (float*)d_out;

    cudaMemsetAsync(out, 0, sizeof(float));

    dim3 grid(IMG_W / TILE, IMG_H / TILE, BATCH);   // 8 x 8 x 4 = 256 blocks
    dim3 block(TILE, TILE);                         // 1024 threads
    containment_loss_kernel<<<grid, block>>>(pred, target, out);
}

// round 3
// speedup vs baseline: 1.0959x; 1.0959x over previous
#include <cuda_runtime.h>
#include <math.h>

// Problem constants
#define IMG_H 256
#define IMG_W 256
#define BATCH 4
#define CHANS 5
#define TILE  32
#define HALO  3                      // dil +-2, conv of dil +-1
#define SIGD  (TILE + 2*HALO)        // 38
#define SIGP  (SIGD + 2)             // padded row
#define HMW   (TILE + 2)             // 34 horizontal-max cols (dil x rel [-1,32])
#define HMP   (HMW + 2)
#define DILD  (TILE + 2)             // 34
#define DILP  (DILD + 2)
#define NBLOCKS 256
#define N_ELEMS (BATCH * IMG_H * IMG_W)

__device__ float        g_part[NBLOCKS];
__device__ unsigned int g_tick;      // zero-initialized; self-resetting ticket

__global__ __launch_bounds__(1024)
void containment_loss_kernel(const float* __restrict__ pred,
                             const float* __restrict__ target,
                             float* __restrict__ out)
{
    __shared__ float s_sig[SIGD][SIGP];   // sigmoid, -inf OOB
    __shared__ float s_hm [SIGD][HMP];    // horizontal 5-max
    __shared__ float s_dil[DILD][DILP];   // full 5x5 dilation, replicate-clamped at fill
    __shared__ float s_red[32];
    __shared__ int   s_last;

    const int b   = blockIdx.z;
    const int ty0 = blockIdx.y * TILE;
    const int tx0 = blockIdx.x * TILE;
    const int py  = threadIdx.y, px = threadIdx.x;
    const int tid = py * TILE + px;
    const int gy  = ty0 + py,   gx = tx0 + px;

    const float* t0 = target + (size_t)b * CHANS * IMG_H * IMG_W;                 // ch 0
    const float* p1 = pred   + (size_t)b * CHANS * IMG_H * IMG_W + IMG_H * IMG_W; // ch 1

    // Prefetch pred value early: DRAM latency overlaps all stencil work below.
    const float pv = p1[gy * IMG_W + gx];

    // ---- Stage 1: sigmoid tile with halo-3; out-of-image = -inf (dilation identity) ----
    #pragma unroll
    for (int i = tid; i < SIGD * SIGD; i += 1024) {
        int iy = i / SIGD, ix = i % SIGD;
        int sy = ty0 + iy - HALO;
        int sx = tx0 + ix - HALO;
        float v = -INFINITY;
        if (sy >= 0 && sy < IMG_H && sx >= 0 && sx < IMG_W) {
            float t = t0[sy * IMG_W + sx];
            float e = __expf(-10.0f * (t - 0.5f));
            v = __fdividef(1.0f, 1.0f + e);
        }
        s_sig[iy][ix] = v;
    }
    __syncthreads();

    // ---- Stage 2a: horizontal 5-max. col ix -> dil-x rel (ix-1), sig cols ix..ix+4 ----
    #pragma unroll
    for (int i = tid; i < SIGD * HMW; i += 1024) {
        int iy = i / HMW, ix = i % HMW;
        float m =        s_sig[iy][ix];
        m = fmaxf(m, s_sig[iy][ix + 1]);
        m = fmaxf(m, s_sig[iy][ix + 2]);
        m = fmaxf(m, s_sig[iy][ix + 3]);
        m = fmaxf(m, s_sig[iy][ix + 4]);
        s_hm[iy][ix] = m;
    }
    __syncthreads();

    // ---- Stage 2b: vertical 5-max, replicate-clamp baked into the index mapping ----
    // s_dil[iy][ix] = dilation at global (clamp(ty0+iy-1), clamp(tx0+ix-1))
    #pragma unroll
    for (int i = tid; i < DILD * DILD; i += 1024) {
        int iy = i / DILD, ix = i % DILD;
        int gyc = min(max(ty0 + iy - 1, 0), IMG_H - 1);
        int gxc = min(max(tx0 + ix - 1, 0), IMG_W - 1);
        int r0 = gyc - ty0 + HALO;     // sig-row of clamped center, in [2,35]
        int c  = gxc - tx0 + 1;        // hm col, in [0,33]
        float m =        s_hm[r0 - 2][c];
        m = fmaxf(m, s_hm[r0 - 1][c]);
        m = fmaxf(m, s_hm[r0    ][c]);
        m = fmaxf(m, s_hm[r0 + 1][c]);
        m = fmaxf(m, s_hm[r0 + 2][c]);
        s_dil[iy][ix] = m;
    }
    __syncthreads();

    // ---- Stage 3: 3x3 weighted sum of (1 - dil); padding already baked in ----
    const float w_e = 0.0574326f;   // exp(-1/0.35)
    const float w_d = 0.0175868f;   // exp(-sqrt(2)/0.35)

    float c00 = s_dil[py    ][px    ], c01 = s_dil[py    ][px + 1], c02 = s_dil[py    ][px + 2];
    float c10 = s_dil[py + 1][px    ], c11 = s_dil[py + 1][px + 1], c12 = s_dil[py + 1][px + 2];
    float c20 = s_dil[py + 2][px    ], c21 = s_dil[py + 2][px + 1], c22 = s_dil[py + 2][px + 2];

    float conv = (1.0f - c11)
               + w_e * (4.0f - (c01 + c10 + c12 + c21))
               + w_d * (4.0f - (c00 + c02 + c20 + c22));

    // distance transform collapses to iteration 0 (boundary monotone, conv > 0 always)
    float cdt = -0.35f * __logf(conv);
    float pen = (cdt > 0.0f) ? fminf(cdt * 0.1f, 1.0f) : 0.0f;
    float viol = pv * (1.0f - c11) * pen;

    // ---- Block reduction ----
    #pragma unroll
    for (int off = 16; off > 0; off >>= 1)
        viol += __shfl_down_sync(0xFFFFFFFFu, viol, off);
    if ((tid & 31) == 0) s_red[tid >> 5] = viol;
    __syncthreads();
    if (tid < 32) {
        float v = s_red[tid];
        #pragma unroll
        for (int off = 16; off > 0; off >>= 1)
            v += __shfl_down_sync(0xFFFFFFFFu, v, off);
        if (tid == 0) {
            int bl = (blockIdx.z * gridDim.y + blockIdx.y) * gridDim.x + blockIdx.x;
            g_part[bl] = v;
            __threadfence();
            unsigned int old = atomicAdd(&g_tick, 1u);
            s_last = (old == NBLOCKS - 1) ? 1 : 0;
        }
    }
    __syncthreads();

    // ---- Last block finalizes: sums the 256 partials, writes mean, resets ticket ----
    if (s_last) {
        __threadfence();
        float v = (tid < NBLOCKS) ? g_part[tid] : 0.0f;
        #pragma unroll
        for (int off = 16; off > 0; off >>= 1)
            v += __shfl_down_sync(0xFFFFFFFFu, v, off);
        if ((tid & 31) == 0) s_red[tid >> 5] = v;
        __syncthreads();
        if (tid < 32) {
            float t = s_red[tid];
            #pragma unroll
            for (int off = 16; off > 0; off >>= 1)
                t += __shfl_down_sync(0xFFFFFFFFu, t, off);
            if (tid == 0) {
                out[0] = t * (1.0f / (float)N_ELEMS);
                g_tick = 0;   // reset for next graph replay
            }
        }
    }
}

extern "C" void kernel_launch(void* const* d_in, const int* in_sizes, int n_in,
                              void* d_out, int out_size)
{
    const float* pred   = (const float*)d_in[0];
    const float* target = (const float*)d_in[1];
    float* out = (float*)d_out;

    dim3 grid(IMG_W / TILE, IMG_H / TILE, BATCH);   // 8 x 8 x 4 = 256 blocks
    dim3 block(TILE, TILE);                         // 1024 threads
    containment_loss_kernel<<<grid, block>>>(pred, target, out);
}

// round 4
// speedup vs baseline: 1.0991x; 1.0029x over previous
#include <cuda_runtime.h>
#include <math.h>

// Problem constants
#define IMG_H 256
#define IMG_W 256
#define BATCH 4
#define CHANS 5
#define TILE_W 64
#define TILE_H 32
#define HALO  3                        // dil +-2, conv of dil +-1
#define SIGH  (TILE_H + 2*HALO)        // 38
#define SIGW  (TILE_W + 2*HALO)        // 70
#define SIGP  (SIGW + 2)               // 72 (stride, bank-skewed)
#define HMW   (TILE_W + 2)             // 66
#define HMP   (HMW + 2)                // 68
#define DILH  (TILE_H + 2)             // 34
#define DILW  (TILE_W + 2)             // 66
#define DILP  (DILW + 2)               // 68
#define NBLOCKS 128
#define N_ELEMS (BATCH * IMG_H * IMG_W)

__device__ float        g_part[NBLOCKS];
__device__ unsigned int g_tick;        // zero-initialized; self-resetting ticket

__global__ __launch_bounds__(1024)
void containment_loss_kernel(const float* __restrict__ pred,
                             const float* __restrict__ target,
                             float* __restrict__ out)
{
    __shared__ float s_sig[SIGH][SIGP];   // sigmoid, -inf OOB
    __shared__ float s_hm [SIGH][HMP];    // horizontal 5-max
    __shared__ float s_dil[DILH][DILP];   // 5x5 dilation, replicate-clamped at fill
    __shared__ float s_red[32];
    __shared__ int   s_last;

    const int b   = blockIdx.z;
    const int ty0 = blockIdx.y * TILE_H;
    const int tx0 = blockIdx.x * TILE_W;
    const int py  = threadIdx.y, px = threadIdx.x;     // px in [0,32); handles px and px+32
    const int tid = py * 32 + px;
    const int gy  = ty0 + py;

    const float* t0 = target + (size_t)b * CHANS * IMG_H * IMG_W;                 // ch 0
    const float* p1 = pred   + (size_t)b * CHANS * IMG_H * IMG_W + IMG_H * IMG_W; // ch 1

    // Prefetch both pred values: DRAM latency overlaps all stencil work below.
    const float pv0 = p1[gy * IMG_W + tx0 + px];
    const float pv1 = p1[gy * IMG_W + tx0 + px + 32];

    // ---- Stage 1: sigmoid tile with halo-3; out-of-image = -inf (dilation identity) ----
    #pragma unroll
    for (int i = tid; i < SIGH * SIGW; i += 1024) {
        int iy = i / SIGW, ix = i % SIGW;
        int sy = ty0 + iy - HALO;
        int sx = tx0 + ix - HALO;
        float v = -INFINITY;
        if (sy >= 0 && sy < IMG_H && sx >= 0 && sx < IMG_W) {
            float t = t0[sy * IMG_W + sx];
            float e = __expf(-10.0f * (t - 0.5f));
            v = __fdividef(1.0f, 1.0f + e);
        }
        s_sig[iy][ix] = v;
    }
    __syncthreads();

    // ---- Stage 2a: horizontal 5-max. col ix -> dil-x rel (ix-1), sig cols ix..ix+4 ----
    #pragma unroll
    for (int i = tid; i < SIGH * HMW; i += 1024) {
        int iy = i / HMW, ix = i % HMW;
        float m =        s_sig[iy][ix];
        m = fmaxf(m, s_sig[iy][ix + 1]);
        m = fmaxf(m, s_sig[iy][ix + 2]);
        m = fmaxf(m, s_sig[iy][ix + 3]);
        m = fmaxf(m, s_sig[iy][ix + 4]);
        s_hm[iy][ix] = m;
    }
    __syncthreads();

    // ---- Stage 2b: vertical 5-max, replicate-clamp baked into the index mapping ----
    // s_dil[iy][ix] = dilation at global (clamp(ty0+iy-1), clamp(tx0+ix-1))
    #pragma unroll
    for (int i = tid; i < DILH * DILW; i += 1024) {
        int iy = i / DILW, ix = i % DILW;
        int gyc = min(max(ty0 + iy - 1, 0), IMG_H - 1);
        int gxc = min(max(tx0 + ix - 1, 0), IMG_W - 1);
        int r0 = gyc - ty0 + HALO;     // sig-row of clamped center, in [2,35]
        int c  = gxc - tx0 + 1;        // hm col, in [0,65]
        float m =        s_hm[r0 - 2][c];
        m = fmaxf(m, s_hm[r0 - 1][c]);
        m = fmaxf(m, s_hm[r0    ][c]);
        m = fmaxf(m, s_hm[r0 + 1][c]);
        m = fmaxf(m, s_hm[r0 + 2][c]);
        s_dil[iy][ix] = m;
    }
    __syncthreads();

    // ---- Stage 3: 3x3 weighted sum of (1 - dil); padding baked in. 2 pixels/thread ----
    const float w_e = 0.0574326f;   // exp(-1/0.35)
    const float w_d = 0.0175868f;   // exp(-sqrt(2)/0.35)

    float acc = 0.0f;
    #pragma unroll
    for (int half = 0; half < 2; half++) {
        int pxx = px + half * 32;
        float c00 = s_dil[py    ][pxx], c01 = s_dil[py    ][pxx + 1], c02 = s_dil[py    ][pxx + 2];
        float c10 = s_dil[py + 1][pxx], c11 = s_dil[py + 1][pxx + 1], c12 = s_dil[py + 1][pxx + 2];
        float c20 = s_dil[py + 2][pxx], c21 = s_dil[py + 2][pxx + 1], c22 = s_dil[py + 2][pxx + 2];

        float conv = (1.0f - c11)
                   + w_e * (4.0f - (c01 + c10 + c12 + c21))
                   + w_d * (4.0f - (c00 + c02 + c20 + c22));

        // distance transform collapses to iteration 0 (boundary monotone, conv > 0 always)
        float cdt = -0.35f * __logf(conv);
        float pen = (cdt > 0.0f) ? fminf(cdt * 0.1f, 1.0f) : 0.0f;
        float pv  = half ? pv1 : pv0;
        acc += pv * (1.0f - c11) * pen;
    }

    // ---- Block reduction ----
    #pragma unroll
    for (int off = 16; off > 0; off >>= 1)
        acc += __shfl_down_sync(0xFFFFFFFFu, acc, off);
    if ((tid & 31) == 0) s_red[tid >> 5] = acc;
    __syncthreads();
    if (tid < 32) {
        float v = s_red[tid];
        #pragma unroll
        for (int off = 16; off > 0; off >>= 1)
            v += __shfl_down_sync(0xFFFFFFFFu, v, off);
        if (tid == 0) {
            int bl = (blockIdx.z * gridDim.y + blockIdx.y) * gridDim.x + blockIdx.x;
            g_part[bl] = v;
            __threadfence();
            unsigned int old = atomicAdd(&g_tick, 1u);
            s_last = (old == NBLOCKS - 1) ? 1 : 0;
        }
    }
    __syncthreads();

    // ---- Last block finalizes: sums the 128 partials, writes mean, resets ticket ----
    if (s_last) {
        __threadfence();
        float v = (tid < NBLOCKS) ? g_part[tid] : 0.0f;
        #pragma unroll
        for (int off = 16; off > 0; off >>= 1)
            v += __shfl_down_sync(0xFFFFFFFFu, v, off);
        if ((tid & 31) == 0) s_red[tid >> 5] = v;
        __syncthreads();
        if (tid < 32) {
            float t = (tid < 4) ? s_red[tid] : 0.0f;
            #pragma unroll
            for (int off = 2; off > 0; off >>= 1)
                t += __shfl_down_sync(0xFFFFFFFFu, t, off);
            if (tid == 0) {
                out[0] = t * (1.0f / (float)N_ELEMS);
                g_tick = 0;   // reset for next graph replay
            }
        }
    }
}

extern "C" void kernel_launch(void* const* d_in, const int* in_sizes, int n_in,
                              void* d_out, int out_size)
{
    const float* pred   = (const float*)d_in[0];
    const float* target = (const float*)d_in[1];
    float* out = (float*)d_out;

    dim3 grid(IMG_W / TILE_W, IMG_H / TILE_H, BATCH);   // 4 x 8 x 4 = 128 blocks
    dim3 block(32, 32);                                 // 1024 threads
    containment_loss_kernel<<<grid, block>>>(pred, target, out);
}

// round 6
// speedup vs baseline: 1.1254x; 1.0239x over previous
#include <cuda_runtime.h>
#include <math.h>

// Problem constants
#define IMG_H 256
#define IMG_W 256
#define BATCH 4
#define CHANS 5
#define TILE_W 64
#define TILE_H 32
#define HALO  3                        // dil +-2, conv of dil +-1
#define SIGH  (TILE_H + 2*HALO)        // 38
#define SIGW  (TILE_W + 2*HALO)        // 70
#define SIGP  (SIGW + 2)               // 72
#define HMW   (TILE_W + 2)             // 66
#define HMP   (HMW + 2)                // 68
#define DILH  (TILE_H + 2)             // 34
#define DILW  (TILE_W + 2)             // 66
#define DILP  (DILW + 2)               // 68
#define NBLOCKS 128
#define N_ELEMS (BATCH * IMG_H * IMG_W)

__device__ float        g_part[NBLOCKS];
__device__ unsigned int g_tick;        // zero-initialized; self-resetting ticket

// Fast reciprocal on the FMA/ALU pipes (keeps MUFU free): bit-trick seed
// (max rel err ~5%) + 2 Newton iterations -> rel err ~6e-6.
__device__ __forceinline__ float frcp_nr(float y)
{
    float r = __int_as_float(0x7EF311C3 - __float_as_int(y));
    r = r * (2.0f - y * r);
    r = r * (2.0f - y * r);
    return r;
}

__global__ __launch_bounds__(1024)
void containment_loss_kernel(const float* __restrict__ pred,
                             const float* __restrict__ target,
                             float* __restrict__ out)
{
    __shared__ float s_raw[SIGH][SIGP];   // raw target, -inf OOB (dilation identity)
    __shared__ float s_hm [SIGH][HMP];    // horizontal 5-max of raw
    __shared__ float s_d  [DILH][DILP];   // d = 1 - sigmoid(10*(dil_raw - 0.5))
    __shared__ float s_red[32];
    __shared__ int   s_last;

    const int b   = blockIdx.z;
    const int ty0 = blockIdx.y * TILE_H;
    const int tx0 = blockIdx.x * TILE_W;
    const int py  = threadIdx.y, px = threadIdx.x;   // px in [0,32); handles px, px+32
    const int tid = py * 32 + px;
    const int gy  = ty0 + py;

    const float* t0 = target + (size_t)b * CHANS * IMG_H * IMG_W;                 // ch 0
    const float* p1 = pred   + (size_t)b * CHANS * IMG_H * IMG_W + IMG_H * IMG_W; // ch 1

    // Prefetch pred values: DRAM latency overlaps the stencil work.
    const float pv0 = p1[gy * IMG_W + tx0 + px];
    const float pv1 = p1[gy * IMG_W + tx0 + px + 32];

    // ---- Stage 1: raw target tile with halo-3 (NO math; sigmoid is monotone,
    //      so dilation commutes with it) ----
    #pragma unroll
    for (int i = tid; i < SIGH * SIGW; i += 1024) {
        int iy = i / SIGW, ix = i % SIGW;
        int sy = ty0 + iy - HALO;
        int sx = tx0 + ix - HALO;
        float v = -INFINITY;
        if (sy >= 0 && sy < IMG_H && sx >= 0 && sx < IMG_W)
            v = t0[sy * IMG_W + sx];
        s_raw[iy][ix] = v;
    }
    __syncthreads();

    // ---- Stage 2a: horizontal 5-max of raw ----
    #pragma unroll
    for (int i = tid; i < SIGH * HMW; i += 1024) {
        int iy = i / HMW, ix = i % HMW;
        float m =        s_raw[iy][ix];
        m = fmaxf(m, s_raw[iy][ix + 1]);
        m = fmaxf(m, s_raw[iy][ix + 2]);
        m = fmaxf(m, s_raw[iy][ix + 3]);
        m = fmaxf(m, s_raw[iy][ix + 4]);
        s_hm[iy][ix] = m;
    }
    __syncthreads();

    // ---- Stage 2b: vertical 5-max (replicate clamp baked in), then
    //      d = 1 - sigmoid(10*(m-0.5)) = 1/(1 + e^{10(m-0.5)}) ----
    //      EX2 on MUFU, reciprocal via Newton on FMA pipe.
    #pragma unroll
    for (int i = tid; i < DILH * DILW; i += 1024) {
        int iy = i / DILW, ix = i % DILW;
        int gyc = min(max(ty0 + iy - 1, 0), IMG_H - 1);
        int gxc = min(max(tx0 + ix - 1, 0), IMG_W - 1);
        int r0 = gyc - ty0 + HALO;     // raw-row of clamped center
        int c  = gxc - tx0 + 1;        // hm col
        float m =        s_hm[r0 - 2][c];
        m = fmaxf(m, s_hm[r0 - 1][c]);
        m = fmaxf(m, s_hm[r0    ][c]);
        m = fmaxf(m, s_hm[r0 + 1][c]);
        m = fmaxf(m, s_hm[r0 + 2][c]);
        float e = __expf(10.0f * (m - 0.5f));     // 1 MUFU (EX2)
        s_d[iy][ix] = frcp_nr(1.0f + e);          // FMA-pipe Newton
    }
    __syncthreads();

    // ---- Stage 3: conv directly from d = (1 - dil); 2 pixels/thread ----
    const float w_e = 0.0574326f;   // exp(-1/0.35)
    const float w_d = 0.0175868f;   // exp(-sqrt(2)/0.35)

    float acc = 0.0f;
    #pragma unroll
    for (int half = 0; half < 2; half++) {
        int pxx = px + half * 32;
        float d00 = s_d[py    ][pxx], d01 = s_d[py    ][pxx + 1], d02 = s_d[py    ][pxx + 2];
        float d10 = s_d[py + 1][pxx], d11 = s_d[py + 1][pxx + 1], d12 = s_d[py + 1][pxx + 2];
        float d20 = s_d[py + 2][pxx], d21 = s_d[py + 2][pxx + 1], d22 = s_d[py + 2][pxx + 2];

        float conv = d11
                   + w_e * (d01 + d10 + d12 + d21)
                   + w_d * (d00 + d02 + d20 + d22);

        // distance transform collapses to iteration 0 (boundary monotone, conv > 0)
        float cdt = -0.35f * __logf(conv);        // 1 MUFU (LG2)
        float pen = (cdt > 0.0f) ? fminf(cdt * 0.1f, 1.0f) : 0.0f;
        float pv  = half ? pv1 : pv0;
        acc += pv * d11 * pen;
    }

    // ---- Block reduction ----
    #pragma unroll
    for (int off = 16; off > 0; off >>= 1)
        acc += __shfl_down_sync(0xFFFFFFFFu, acc, off);
    if ((tid & 31) == 0) s_red[tid >> 5] = acc;
    __syncthreads();
    if (tid < 32) {
        float v = s_red[tid];
        #pragma unroll
        for (int off = 16; off > 0; off >>= 1)
            v += __shfl_down_sync(0xFFFFFFFFu, v, off);
        if (tid == 0) {
            int bl = (blockIdx.z * gridDim.y + blockIdx.y) * gridDim.x + blockIdx.x;
            g_part[bl] = v;
            __threadfence();
            unsigned int old = atomicAdd(&g_tick, 1u);
            s_last = (old == NBLOCKS - 1) ? 1 : 0;
        }
    }
    __syncthreads();

    // ---- Last block finalizes: sums the 128 partials, writes mean, resets ticket ----
    if (s_last) {
        __threadfence();
        float v = (tid < NBLOCKS) ? g_part[tid] : 0.0f;
        #pragma unroll
        for (int off = 16; off > 0; off >>= 1)
            v += __shfl_down_sync(0xFFFFFFFFu, v, off);
        if ((tid & 31) == 0) s_red[tid >> 5] = v;
        __syncthreads();
        if (tid < 32) {
            float t = (tid < 4) ? s_red[tid] : 0.0f;
            #pragma unroll
            for (int off = 2; off > 0; off >>= 1)
                t += __shfl_down_sync(0xFFFFFFFFu, t, off);
            if (tid == 0) {
                out[0] = t * (1.0f / (float)N_ELEMS);
                g_tick = 0;   // reset for next graph replay
            }
        }
    }
}

extern "C" void kernel_launch(void* const* d_in, const int* in_sizes, int n_in,
                              void* d_out, int out_size)
{
    const float* pred   = (const float*)d_in[0];
    const float* target = (const float*)d_in[1];
    float* out = (float*)d_out;

    dim3 grid(IMG_W / TILE_W, IMG_H / TILE_H, BATCH);   // 4 x 8 x 4 = 128 blocks
    dim3 block(32, 32);                                 // 1024 threads
    containment_loss_kernel<<<grid, block>>>(pred, target, out);
}

// round 7
// speedup vs baseline: 1.3464x; 1.1964x over previous
#include <cuda_runtime.h>
#include <math.h>

// Problem constants
#define IMG_H 256
#define IMG_W 256
#define BATCH 4
#define CHANS 5
#define TILE_W 32
#define TILE_H 16
#define BLOCK  128
#define HALO  3                        // dil +-2, conv of dil +-1
#define SIGH  (TILE_H + 2*HALO)        // 22
#define SIGW  (TILE_W + 2*HALO)        // 38
#define SIGP  (SIGW + 2)               // 40
#define HMW   (TILE_W + 2)             // 34
#define HMP   (HMW + 2)                // 36
#define DILH  (TILE_H + 2)             // 18
#define DILW  (TILE_W + 2)             // 34
#define DILP  (DILW + 2)               // 36
#define NBLOCKS 512
#define N_ELEMS (BATCH * IMG_H * IMG_W)

__device__ float        g_sum;         // zero-initialized; self-resetting
__device__ unsigned int g_tick;        // zero-initialized; self-resetting ticket

// Fast reciprocal on the FMA pipe: bit-trick seed + 2 Newton -> rel err ~6e-6.
__device__ __forceinline__ float frcp_nr(float y)
{
    float r = __int_as_float(0x7EF311C3 - __float_as_int(y));
    r = r * (2.0f - y * r);
    r = r * (2.0f - y * r);
    return r;
}

__global__ __launch_bounds__(BLOCK)
void containment_loss_kernel(const float* __restrict__ pred,
                             const float* __restrict__ target,
                             float* __restrict__ out)
{
    __shared__ float s_raw[SIGH][SIGP];   // raw target, -inf OOB (dilation identity)
    __shared__ float s_hm [SIGH][HMP];    // horizontal 5-max of raw
    __shared__ float s_d  [DILH][DILP];   // d = 1 - sigmoid(10*(dil_raw - 0.5))
    __shared__ float s_red[4];

    const int b   = blockIdx.z;
    const int ty0 = blockIdx.y * TILE_H;
    const int tx0 = blockIdx.x * TILE_W;
    const int tid = threadIdx.x;
    const int px  = tid & 31;            // 0..31
    const int py  = tid >> 5;            // 0..3; thread handles rows py, py+4, py+8, py+12

    const float* t0 = target + (size_t)b * CHANS * IMG_H * IMG_W;                 // ch 0
    const float* p1 = pred   + (size_t)b * CHANS * IMG_H * IMG_W + IMG_H * IMG_W; // ch 1

    // Prefetch the 4 pred values: DRAM latency overlaps all stencil work.
    float pv[4];
    #pragma unroll
    for (int k = 0; k < 4; k++)
        pv[k] = p1[(ty0 + py + 4 * k) * IMG_W + tx0 + px];

    // ---- Stage 1: raw target tile with halo-3 (sigmoid commutes with max) ----
    #pragma unroll
    for (int i = tid; i < SIGH * SIGW; i += BLOCK) {
        int iy = i / SIGW, ix = i % SIGW;
        int sy = ty0 + iy - HALO;
        int sx = tx0 + ix - HALO;
        float v = -INFINITY;
        if (sy >= 0 && sy < IMG_H && sx >= 0 && sx < IMG_W)
            v = t0[sy * IMG_W + sx];
        s_raw[iy][ix] = v;
    }
    __syncthreads();

    // ---- Stage 2a: horizontal 5-max of raw ----
    #pragma unroll
    for (int i = tid; i < SIGH * HMW; i += BLOCK) {
        int iy = i / HMW, ix = i % HMW;
        float m =        s_raw[iy][ix];
        m = fmaxf(m, s_raw[iy][ix + 1]);
        m = fmaxf(m, s_raw[iy][ix + 2]);
        m = fmaxf(m, s_raw[iy][ix + 3]);
        m = fmaxf(m, s_raw[iy][ix + 4]);
        s_hm[iy][ix] = m;
    }
    __syncthreads();

    // ---- Stage 2b: vertical 5-max (replicate clamp baked in), then
    //      d = 1/(1 + e^{10(m-0.5)}): EX2 on MUFU, reciprocal on FMA pipe ----
    #pragma unroll
    for (int i = tid; i < DILH * DILW; i += BLOCK) {
        int iy = i / DILW, ix = i % DILW;
        int gyc = min(max(ty0 + iy - 1, 0), IMG_H - 1);
        int gxc = min(max(tx0 + ix - 1, 0), IMG_W - 1);
        int r0 = gyc - ty0 + HALO;     // raw-row of clamped center
        int c  = gxc - tx0 + 1;        // hm col
        float m =        s_hm[r0 - 2][c];
        m = fmaxf(m, s_hm[r0 - 1][c]);
        m = fmaxf(m, s_hm[r0    ][c]);
        m = fmaxf(m, s_hm[r0 + 1][c]);
        m = fmaxf(m, s_hm[r0 + 2][c]);
        float e = __expf(10.0f * (m - 0.5f));
        s_d[iy][ix] = frcp_nr(1.0f + e);
    }
    __syncthreads();

    // ---- Stage 3: conv from d = (1 - dil); 4 pixels/thread ----
    const float w_e = 0.0574326f;   // exp(-1/0.35)
    const float w_d = 0.0175868f;   // exp(-sqrt(2)/0.35)

    float acc = 0.0f;
    #pragma unroll
    for (int k = 0; k < 4; k++) {
        int ry = py + 4 * k;            // dil row base = ry (since s_d row iy = out row iy-? )
        float d00 = s_d[ry    ][px    ], d01 = s_d[ry    ][px + 1], d02 = s_d[ry    ][px + 2];
        float d10 = s_d[ry + 1][px    ], d11 = s_d[ry + 1][px + 1], d12 = s_d[ry + 1][px + 2];
        float d20 = s_d[ry + 2][px    ], d21 = s_d[ry + 2][px + 1], d22 = s_d[ry + 2][px + 2];

        float conv = d11
                   + w_e * (d01 + d10 + d12 + d21)
                   + w_d * (d00 + d02 + d20 + d22);

        // distance transform collapses to iteration 0 (boundary monotone, conv > 0)
        float cdt = -0.35f * __logf(conv);
        float pen = (cdt > 0.0f) ? fminf(cdt * 0.1f, 1.0f) : 0.0f;
        acc += pv[k] * d11 * pen;
    }

    // ---- Block reduction (4 warps) ----
    #pragma unroll
    for (int off = 16; off > 0; off >>= 1)
        acc += __shfl_down_sync(0xFFFFFFFFu, acc, off);
    if (px == 0) s_red[py] = acc;
    __syncthreads();

    if (tid == 0) {
        float v = s_red[0] + s_red[1] + s_red[2] + s_red[3];
        atomicAdd(&g_sum, v);
        __threadfence();
        unsigned int old = atomicAdd(&g_tick, 1u);
        if (old == NBLOCKS - 1) {
            __threadfence();
            out[0] = g_sum * (1.0f / (float)N_ELEMS);
            g_sum  = 0.0f;   // reset for next graph replay
            g_tick = 0u;
        }
    }
}

extern "C" void kernel_launch(void* const* d_in, const int* in_sizes, int n_in,
                              void* d_out, int out_size)
{
    const float* pred   = (const float*)d_in[0];
    const float* target = (const float*)d_in[1];
    float* out = (float*)d_out;

    dim3 grid(IMG_W / TILE_W, IMG_H / TILE_H, BATCH);   // 8 x 16 x 4 = 512 blocks
    dim3 block(BLOCK);                                  // 128 threads
    containment_loss_kernel<<<grid, block>>>(pred, target, out);
}